// round 2
// baseline (speedup 1.0000x reference)
#include <cuda_runtime.h>
#include <cuda_bf16.h>
#include <math.h>

// Problem constants (fixed by setup_inputs)
#define BATCH 2
#define SEQ 128
#define MODEL_DIM 256
#define NUM_HEAD 8
#define HEAD_DIM 32
#define ROWS (BATCH * SEQ * SEQ)        // 32768 token rows
#define QKV_DIM (3 * MODEL_DIM)         // 768
#define LN_EPS 1e-5f
#define MASK_BIAS -1000000000.0f
#define SCALE 0.17677669529663687f      // 32^-0.5

// Scratch (device globals; no allocations allowed)
__device__ float g_xnorm[ROWS * MODEL_DIM];
__device__ float g_qkv[ROWS * QKV_DIM];
__device__ float g_att[ROWS * MODEL_DIM];
__device__ int   g_mask_kind;           // 0=u8 bytes, 1=int32, 2=float32

// ---------------------------------------------------------------------------
// Mask dtype probe: bool arrays may arrive as u8, i32 or f32. Deterministic.
// ---------------------------------------------------------------------------
__global__ void detect_mask_kernel(const unsigned char* __restrict__ p) {
    if (threadIdx.x == 0 && blockIdx.x == 0) {
        int nzoff = 0, maxb = 0;
        for (int i = 0; i < 4096; i++) {
            int v = p[i];
            if (v > maxb) maxb = v;
            if ((i & 3) != 0 && v != 0) nzoff = 1;
        }
        // int32 {0,1}: all non-word-aligned bytes zero.
        // u8 {0,1}: nonzero bytes at odd offsets, max <= 1.
        // f32 {0.0,1.0}: 0x3f800000 pattern -> max byte 0x80 > 1.
        g_mask_kind = nzoff ? (maxb > 1 ? 2 : 0) : 1;
    }
}

// ---------------------------------------------------------------------------
// LayerNorm: one warp per 256-wide row
// ---------------------------------------------------------------------------
__global__ __launch_bounds__(256) void ln_kernel(
    const float* __restrict__ x, const float* __restrict__ gamma,
    const float* __restrict__ beta, float* __restrict__ out) {
    int row = blockIdx.x * 8 + threadIdx.y;
    int lane = threadIdx.x;
    const float* xr = x + (size_t)row * MODEL_DIM;
    float v[8];
    float s = 0.f, s2 = 0.f;
#pragma unroll
    for (int i = 0; i < 8; i++) {
        v[i] = xr[lane + i * 32];
        s += v[i];
        s2 += v[i] * v[i];
    }
#pragma unroll
    for (int o = 16; o; o >>= 1) {
        s += __shfl_xor_sync(0xffffffffu, s, o);
        s2 += __shfl_xor_sync(0xffffffffu, s2, o);
    }
    float mean = s * (1.f / 256.f);
    float var = s2 * (1.f / 256.f) - mean * mean;
    float inv = rsqrtf(var + LN_EPS);
    float* orow = out + (size_t)row * MODEL_DIM;
#pragma unroll
    for (int i = 0; i < 8; i++) {
        int c = lane + i * 32;
        orow[c] = (v[i] - mean) * inv * gamma[c] + beta[c];
    }
}

// ---------------------------------------------------------------------------
// GEMM: C[M,N] = A[M,K] * W[N,K]^T  (fp32, 128x128x8 tiles, 8x8 microtile)
// ---------------------------------------------------------------------------
#define BM 128
#define BN 128
#define BK 8

__global__ __launch_bounds__(256) void gemm_xwT(
    const float* __restrict__ A, const float* __restrict__ W,
    float* __restrict__ C, int M, int N, int K) {
    __shared__ float As[BK][BM + 4];
    __shared__ float Bs[BK][BN + 4];
    int tid = threadIdx.x;
    int tx = tid & 15;
    int ty = tid >> 4;
    int m0 = blockIdx.y * BM;
    int n0 = blockIdx.x * BN;
    const float* Ab = A + (size_t)m0 * K;
    const float* Wb = W + (size_t)n0 * K;
    float acc[8][8];
#pragma unroll
    for (int i = 0; i < 8; i++)
#pragma unroll
        for (int j = 0; j < 8; j++) acc[i][j] = 0.f;

    int lr = tid >> 1;
    int lk = (tid & 1) * 4;
    for (int k0 = 0; k0 < K; k0 += BK) {
        float4 av = *(const float4*)(Ab + (size_t)lr * K + k0 + lk);
        float4 wv = *(const float4*)(Wb + (size_t)lr * K + k0 + lk);
        __syncthreads();
        As[lk + 0][lr] = av.x; As[lk + 1][lr] = av.y;
        As[lk + 2][lr] = av.z; As[lk + 3][lr] = av.w;
        Bs[lk + 0][lr] = wv.x; Bs[lk + 1][lr] = wv.y;
        Bs[lk + 2][lr] = wv.z; Bs[lk + 3][lr] = wv.w;
        __syncthreads();
#pragma unroll
        for (int kk = 0; kk < BK; kk++) {
            float a[8], b[8];
            *(float4*)(a + 0) = *(const float4*)&As[kk][ty * 8 + 0];
            *(float4*)(a + 4) = *(const float4*)&As[kk][ty * 8 + 4];
            *(float4*)(b + 0) = *(const float4*)&Bs[kk][tx * 8 + 0];
            *(float4*)(b + 4) = *(const float4*)&Bs[kk][tx * 8 + 4];
#pragma unroll
            for (int i = 0; i < 8; i++)
#pragma unroll
                for (int j = 0; j < 8; j++) acc[i][j] += a[i] * b[j];
        }
    }
#pragma unroll
    for (int i = 0; i < 8; i++) {
        int m = m0 + ty * 8 + i;
        float* Cr = C + (size_t)m * N + n0 + tx * 8;
        float4 o0 = make_float4(acc[i][0], acc[i][1], acc[i][2], acc[i][3]);
        float4 o1 = make_float4(acc[i][4], acc[i][5], acc[i][6], acc[i][7]);
        *(float4*)(Cr + 0) = o0;
        *(float4*)(Cr + 4) = o1;
    }
}

// ---------------------------------------------------------------------------
// Axial rotary: only channels [0,32) of q and of k sections. 8 rows per block,
// 32 threads per row (16 q pairs + 16 k pairs).
// ---------------------------------------------------------------------------
__global__ __launch_bounds__(256) void rope_kernel(float* __restrict__ qkv) {
    int row = blockIdx.x * 8 + (threadIdx.x >> 5);
    int t = threadIdx.x & 31;
    int sec = t >> 4;          // 0 = q, 1 = k
    int p = t & 15;            // pair index within the 32 rot channels
    int x = (row >> 7) & 127;
    int y = row & 127;
    int pos = (p < 8) ? x : y;
    int j = p & 7;
    float tl = -1.f + 2.f * (float)pos * (1.f / 127.f);
    // inv_freq[j] = 10000^(-2j/16) = exp(-ln(10000)/8 * j)
    float invf = expf(-1.1512925464970229f * (float)j);
    float theta = tl * invf;
    float c, s;
    sincosf(theta, &s, &c);
    float* base = qkv + (size_t)row * QKV_DIM + sec * MODEL_DIM + 2 * p;
    float a = base[0];
    float b = base[1];
    base[0] = a * c - b * s;
    base[1] = b * c + a * s;
}

// ---------------------------------------------------------------------------
// Attention: one CTA per (b*x, head). 128 threads, thread t owns q-row y=t.
// K/V tiles + full exp-score row in smem (~97KB dynamic).
// ---------------------------------------------------------------------------
__global__ __launch_bounds__(128) void attn_kernel(
    const float* __restrict__ qkv, const void* __restrict__ pmask,
    float* __restrict__ out) {
    int h = blockIdx.x & 7;
    int bx = blockIdx.x >> 3;       // b*128 + x
    extern __shared__ float sm[];
    float* Ks = sm;                 // 128*32
    float* Vs = Ks + 128 * 32;      // 128*32
    float* S  = Vs + 128 * 32;      // 128*129 (scores; also q staging)
    float* Ms = S + 128 * 129;      // 128 mask biases
    int t = threadIdx.x;
    size_t rowbase = (size_t)bx * 128;
    const float* base = qkv + rowbase * QKV_DIM;

    // K, V tiles (coalesced)
    for (int e = t; e < 128 * 32; e += 128) {
        int y = e >> 5, d = e & 31;
        Ks[e] = base[(size_t)y * QKV_DIM + MODEL_DIM + h * HEAD_DIM + d];
        Vs[e] = base[(size_t)y * QKV_DIM + 2 * MODEL_DIM + h * HEAD_DIM + d];
    }
    // Q staged into S with pad-33 rows for conflict-free per-row reads
    for (int e = t; e < 128 * 32; e += 128) {
        int y = e >> 5, d = e & 31;
        S[y * 33 + d] = base[(size_t)y * QKV_DIM + h * HEAD_DIM + d];
    }
    // mask bias
    {
        int kind = g_mask_kind;
        size_t midx = (size_t)bx * 128 + t;
        bool mset;
        if (kind == 0)      mset = ((const unsigned char*)pmask)[midx] != 0;
        else if (kind == 1) mset = ((const int*)pmask)[midx] != 0;
        else                mset = ((const float*)pmask)[midx] != 0.f;
        Ms[t] = mset ? 1.f : 0.f;
    }
    __syncthreads();

    float q[32];
#pragma unroll
    for (int d = 0; d < 32; d++) q[d] = S[t * 33 + d];
    __syncthreads();   // all q reads done before S is reused for scores

    float mx = -1e30f;
    for (int k = 0; k < 128; k++) {
        const float4* kr = (const float4*)&Ks[k * 32];
        float s = 0.f;
#pragma unroll
        for (int jj = 0; jj < 8; jj++) {
            float4 kv = kr[jj];
            s += q[4 * jj + 0] * kv.x + q[4 * jj + 1] * kv.y +
                 q[4 * jj + 2] * kv.z + q[4 * jj + 3] * kv.w;
        }
        s = (Ms[k] != 0.f) ? MASK_BIAS : s * SCALE;
        S[t * 129 + k] = s;
        mx = fmaxf(mx, s);
    }
    float l = 0.f;
    for (int k = 0; k < 128; k++) {
        float p = __expf(S[t * 129 + k] - mx);
        S[t * 129 + k] = p;
        l += p;
    }
    float inv = 1.f / l;

    float acc[32];
#pragma unroll
    for (int d = 0; d < 32; d++) acc[d] = 0.f;
    for (int k = 0; k < 128; k++) {
        float p = S[t * 129 + k];
        const float4* vr = (const float4*)&Vs[k * 32];
#pragma unroll
        for (int jj = 0; jj < 8; jj++) {
            float4 vv = vr[jj];
            acc[4 * jj + 0] += p * vv.x;
            acc[4 * jj + 1] += p * vv.y;
            acc[4 * jj + 2] += p * vv.z;
            acc[4 * jj + 3] += p * vv.w;
        }
    }
    float* orow = out + (rowbase + t) * MODEL_DIM + h * HEAD_DIM;
#pragma unroll
    for (int jj = 0; jj < 8; jj++) {
        float4 o = make_float4(acc[4 * jj + 0] * inv, acc[4 * jj + 1] * inv,
                               acc[4 * jj + 2] * inv, acc[4 * jj + 3] * inv);
        *(float4*)(orow + 4 * jj) = o;
    }
}

// ---------------------------------------------------------------------------
extern "C" void kernel_launch(void* const* d_in, const int* in_sizes, int n_in,
                              void* d_out, int out_size) {
    const float* pair_act = (const float*)d_in[0];
    const void*  pair_mask = d_in[1];
    const float* ln_gamma = (const float*)d_in[2];
    const float* ln_beta  = (const float*)d_in[3];
    const float* Wqkv = (const float*)d_in[4];
    const float* Wout = (const float*)d_in[5];
    float* out = (float*)d_out;

    float* xnorm; cudaGetSymbolAddress((void**)&xnorm, g_xnorm);
    float* qkv;   cudaGetSymbolAddress((void**)&qkv, g_qkv);
    float* att;   cudaGetSymbolAddress((void**)&att, g_att);

    detect_mask_kernel<<<1, 32>>>((const unsigned char*)pair_mask);

    ln_kernel<<<ROWS / 8, dim3(32, 8)>>>(pair_act, ln_gamma, ln_beta, xnorm);

    gemm_xwT<<<dim3(QKV_DIM / BN, ROWS / BM), 256>>>(
        xnorm, Wqkv, qkv, ROWS, QKV_DIM, MODEL_DIM);

    rope_kernel<<<ROWS / 8, 256>>>(qkv);

    int attn_smem = (128 * 32 * 2 + 128 * 129 + 128) * (int)sizeof(float);
    cudaFuncSetAttribute(attn_kernel,
                         cudaFuncAttributeMaxDynamicSharedMemorySize, attn_smem);
    attn_kernel<<<BATCH * SEQ * NUM_HEAD, 128, attn_smem>>>(qkv, pair_mask, att);

    gemm_xwT<<<dim3(MODEL_DIM / BN, ROWS / BM), 256>>>(
        att, Wout, out, ROWS, MODEL_DIM, MODEL_DIM);
}